// round 6
// baseline (speedup 1.0000x reference)
#include <cuda_runtime.h>
#include <cuda_fp16.h>
#include <stdint.h>

#define S_LEN 2048
#define DH    128
#define BH    64
#define NT    256
#define QT_ROWS 128
#define KT_ROWS 64

#define ELEMS ((size_t)BH * S_LEN * DH)
#define PAIRS (ELEMS / 2)

// fp16 scratch: K hi/lo, V hi
__device__ __align__(16) __half g_kh[ELEMS];
__device__ __align__(16) __half g_kl[ELEMS];
__device__ __align__(16) __half g_vh[ELEMS];

// SMEM: Q hi 32KB + three 48KB stages {Kh,Kl,Vh} = 176KB
#define SM_QH   0u
#define SM_ST0  32768u
#define STAGE_B 49152u
#define OFF_KL  16384u
#define OFF_VH  32768u
#define SM_TOTAL (32768 + 3 * 49152)

__device__ __forceinline__ uint32_t pack2h(float x, float y) {
    __half2 h = __floats2half2_rn(x, y);
    return *(uint32_t*)&h;
}
__device__ __forceinline__ void split2h(float x, float y, uint32_t& h, uint32_t& l) {
    __half hx = __float2half_rn(x);
    __half hy = __float2half_rn(y);
    __half lx = __float2half_rn(x - __half2float(hx));
    __half ly = __float2half_rn(y - __half2float(hy));
    h = (uint32_t)__half_as_ushort(hx) | ((uint32_t)__half_as_ushort(hy) << 16);
    l = (uint32_t)__half_as_ushort(lx) | ((uint32_t)__half_as_ushort(ly) << 16);
}

__global__ void split_prep(const float* __restrict__ K, const float* __restrict__ V)
{
    const float2* k2 = (const float2*)K;
    const float2* v2 = (const float2*)V;
    uint32_t* kh = (uint32_t*)g_kh; uint32_t* kl = (uint32_t*)g_kl;
    uint32_t* vh = (uint32_t*)g_vh;
    size_t stride = (size_t)gridDim.x * blockDim.x;
    for (size_t i = (size_t)blockIdx.x * blockDim.x + threadIdx.x; i < PAIRS; i += stride) {
        float2 v; uint32_t h, l;
        v = k2[i]; split2h(v.x, v.y, h, l); kh[i] = h; kl[i] = l;
        v = v2[i]; vh[i] = pack2h(v.x, v.y);
    }
}

__device__ __forceinline__ uint32_t smem_u32(const void* p) {
    uint32_t a;
    asm("{ .reg .u64 t; cvta.to.shared.u64 t, %1; cvt.u32.u64 %0, t; }" : "=r"(a) : "l"(p));
    return a;
}
__device__ __forceinline__ void cpa16(uint32_t dst, const void* src) {
    asm volatile("cp.async.cg.shared.global [%0], [%1], 16;" :: "r"(dst), "l"(src));
}
#define CP_COMMIT() asm volatile("cp.async.commit_group;" ::: "memory")
#define CP_WAIT1()  asm volatile("cp.async.wait_group 1;" ::: "memory")
#define CP_WAIT0()  asm volatile("cp.async.wait_group 0;" ::: "memory")

#define LDSM_X4(r0,r1,r2,r3,a) \
    asm volatile("ldmatrix.sync.aligned.m8n8.x4.shared.b16 {%0,%1,%2,%3},[%4];" \
                 : "=r"(r0),"=r"(r1),"=r"(r2),"=r"(r3) : "r"(a))
#define LDSM_X4T(r0,r1,r2,r3,a) \
    asm volatile("ldmatrix.sync.aligned.m8n8.x4.trans.shared.b16 {%0,%1,%2,%3},[%4];" \
                 : "=r"(r0),"=r"(r1),"=r"(r2),"=r"(r3) : "r"(a))
#define MMA(c,a0,a1,a2,a3,b0,b1) \
    asm volatile("mma.sync.aligned.m16n8k16.row.col.f32.f16.f16.f32 " \
                 "{%0,%1,%2,%3},{%4,%5,%6,%7},{%8,%9},{%0,%1,%2,%3};" \
                 : "+f"((c)[0]),"+f"((c)[1]),"+f"((c)[2]),"+f"((c)[3]) \
                 : "r"(a0),"r"(a1),"r"(a2),"r"(a3),"r"(b0),"r"(b1))

__global__ __launch_bounds__(NT, 1)
void fa_mma_kernel(const float* __restrict__ Qg_all, float* __restrict__ Og)
{
    extern __shared__ __align__(16) char sm8[];
    const uint32_t smb = smem_u32(sm8);
    const int tid = threadIdx.x;
    const int w = tid >> 5, l = tid & 31;

    const int qt = (int)gridDim.x - 1 - (int)blockIdx.x;   // heaviest first
    const int bh = blockIdx.y;
    const size_t gbase = (size_t)bh * S_LEN * DH;
    const int ntk = 2 * qt + 2;                            // always even
    const float scale = 0.08838834764831845f;              // 1/sqrt(128)

    // ---- Q prologue: load f32, pre-scale, round to fp16 (hi only) ----
    {
        const float4* q4 = (const float4*)(Qg_all + gbase + (size_t)qt * QT_ROWS * DH);
        #pragma unroll
        for (int i = 0; i < 8; i++) {
            int it  = tid + i * NT;          // 128 rows x 16 chunks
            int row = it >> 4, ch = it & 15;
            float4 f0 = q4[row * 32 + ch * 2];
            float4 f1 = q4[row * 32 + ch * 2 + 1];
            uint4 hq = make_uint4(pack2h(f0.x*scale, f0.y*scale),
                                  pack2h(f0.z*scale, f0.w*scale),
                                  pack2h(f1.x*scale, f1.y*scale),
                                  pack2h(f1.z*scale, f1.w*scale));
            *(uint4*)(sm8 + SM_QH + (row << 8) + ((ch ^ (row & 7)) << 4)) = hq;
        }
    }

    auto load_kv = [&](uint32_t st, int kti) {
        const size_t gb = gbase + (size_t)kti * KT_ROWS * DH;
        #pragma unroll
        for (int i = 0; i < 12; i++) {
            int it  = tid + i * NT;          // 3 arrays x 64 rows x 16 chunks
            int arr = it >> 10;
            int row = (it >> 4) & 63;
            int ch  = it & 15;
            uint32_t dst = st + (uint32_t)arr * 16384u + (row << 8) + ((ch ^ (row & 7)) << 4);
            const __half* sp = (arr == 0) ? g_kh : (arr == 1) ? g_kl : g_vh;
            cpa16(dst, sp + gb + (size_t)row * DH + ch * 8);
        }
    };

    float Oa[16][4];
    #pragma unroll
    for (int i = 0; i < 16; i++) { Oa[i][0]=Oa[i][1]=Oa[i][2]=Oa[i][3]=0.f; }
    float lsum0 = 0.f, lsum1 = 0.f;

    const int grow0  = qt * QT_ROWS + 16 * w + (l >> 2);
    const int rowmax = qt * QT_ROWS + 16 * w + 15;
    const uint32_t qrowaddr = smb + SM_QH + (uint32_t)((16 * w + (l & 15)) << 8);
    const int aswz = l & 7;
    const int ainc = l >> 4;

    // one QK k-step (2-term): 1 Q LDSM, 8 K LDSM, 16 MMAs into S
    auto qk_step = [&](float (&S)[8][4], uint32_t sKH, int ks) {
        uint32_t qh0,qh1,qh2,qh3;
        uint32_t qa = qrowaddr + (uint32_t)(((2*ks + ainc) ^ aswz) << 4);
        LDSM_X4(qh0,qh1,qh2,qh3, qa);
        uint32_t kh[16], kl[16];
        #pragma unroll
        for (int p = 0; p < 4; p++) {
            uint32_t ka = sKH + (uint32_t)((8*(2*p + (l>>4)) + (l & 7)) << 8)
                              + (uint32_t)(((2*ks + ((l>>3)&1)) ^ aswz) << 4);
            LDSM_X4(kh[4*p],kh[4*p+1],kh[4*p+2],kh[4*p+3], ka);
            LDSM_X4(kl[4*p],kl[4*p+1],kl[4*p+2],kl[4*p+3], ka + OFF_KL);
        }
        #pragma unroll
        for (int p = 0; p < 4; p++) {
            MMA(S[2*p],   qh0,qh1,qh2,qh3, kh[4*p],  kh[4*p+1]);
            MMA(S[2*p+1], qh0,qh1,qh2,qh3, kh[4*p+2],kh[4*p+3]);
        }
        #pragma unroll
        for (int p = 0; p < 4; p++) {
            MMA(S[2*p],   qh0,qh1,qh2,qh3, kl[4*p],  kl[4*p+1]);
            MMA(S[2*p+1], qh0,qh1,qh2,qh3, kl[4*p+2],kl[4*p+3]);
        }
    };

    // one pipelined iteration: softmax+PV(tile t, scores Sc, stage stC)
    // interleaved with QK(tile t+1, into Sn, stage stN); prefetch t+2 into stL
    auto body = [&](int t, float (&Sc)[8][4], float (&Sn)[8][4],
                    uint32_t stC, uint32_t stN, uint32_t stL) {
        CP_WAIT0();                 // stages t, t+1 resident & visible after sync
        __syncthreads();            // also: all warps done reading slot stL (tile t-1)
        if (t + 2 < ntk) load_kv(stL, t + 2);
        CP_COMMIT();

        const int kbase = t * KT_ROWS;
        const bool activeC = (kbase <= rowmax);                          // tile t work
        const bool activeN = (t + 1 < ntk) && (kbase + KT_ROWS <= rowmax); // tile t+1 QK
        const bool wfull   = (kbase + KT_ROWS - 1) <= (qt * QT_ROWS + 16 * w);
        const uint32_t sVH = stC + OFF_VH;

        if (activeN) {
            #pragma unroll
            for (int i = 0; i < 8; i++) { Sn[i][0]=Sn[i][1]=Sn[i][2]=Sn[i][3]=0.f; }
        }

        #pragma unroll
        for (int kv = 0; kv < 4; kv++) {
            uint32_t ph[4], pl[4], vh[32];
            if (activeC) {          // exp + split P (tile t)
                #pragma unroll
                for (int q = 0; q < 2; q++) {
                    int nn = 2*kv + q;
                    float p00, p01, p10, p11;
                    if (wfull) {
                        p00 = __expf(Sc[nn][0]); p01 = __expf(Sc[nn][1]);
                        p10 = __expf(Sc[nn][2]); p11 = __expf(Sc[nn][3]);
                    } else {
                        int kc = kbase + 8 * nn + 2 * (l & 3);
                        p00 = (kc     <= grow0    ) ? __expf(Sc[nn][0]) : 0.f;
                        p01 = (kc + 1 <= grow0    ) ? __expf(Sc[nn][1]) : 0.f;
                        p10 = (kc     <= grow0 + 8) ? __expf(Sc[nn][2]) : 0.f;
                        p11 = (kc + 1 <= grow0 + 8) ? __expf(Sc[nn][3]) : 0.f;
                    }
                    lsum0 += p00 + p01;
                    lsum1 += p10 + p11;
                    split2h(p00, p01, ph[2*q],   pl[2*q]);
                    split2h(p10, p11, ph[2*q+1], pl[2*q+1]);
                }
            }
            if (activeN) qk_step(Sn, stN, 2*kv);         // hides MUFU/split latency
            if (activeC) {
                #pragma unroll
                for (int p2 = 0; p2 < 8; p2++) {
                    uint32_t va = sVH + (uint32_t)((16*kv + (l & 15)) << 8)
                                      + (uint32_t)(((2*p2 + (l>>4)) ^ aswz) << 4);
                    LDSM_X4T(vh[4*p2],vh[4*p2+1],vh[4*p2+2],vh[4*p2+3], va);
                }
                #pragma unroll
                for (int p2 = 0; p2 < 8; p2++) {         // sweep 1: Ph * Vh
                    MMA(Oa[2*p2],   ph[0],ph[1],ph[2],ph[3], vh[4*p2],  vh[4*p2+1]);
                    MMA(Oa[2*p2+1], ph[0],ph[1],ph[2],ph[3], vh[4*p2+2],vh[4*p2+3]);
                }
            }
            if (activeN) qk_step(Sn, stN, 2*kv + 1);     // hides V-LDSM latency
            if (activeC) {
                #pragma unroll
                for (int p2 = 0; p2 < 8; p2++) {         // sweep 2: Pl * Vh
                    MMA(Oa[2*p2],   pl[0],pl[1],pl[2],pl[3], vh[4*p2],  vh[4*p2+1]);
                    MMA(Oa[2*p2+1], pl[0],pl[1],pl[2],pl[3], vh[4*p2+2],vh[4*p2+3]);
                }
            }
        }
    };

    // ---- pipeline prologue: stages 0,1 in flight; compute QK(0) ----
    const uint32_t stb = smb + SM_ST0;
    load_kv(stb, 0);
    CP_COMMIT();
    load_kv(stb + STAGE_B, 1);
    CP_COMMIT();

    float SaA[8][4], SaB[8][4];
    CP_WAIT1();                 // stage 0 done (stage 1 may be in flight)
    __syncthreads();
    #pragma unroll
    for (int i = 0; i < 8; i++) { SaA[i][0]=SaA[i][1]=SaA[i][2]=SaA[i][3]=0.f; }
    #pragma unroll
    for (int ks = 0; ks < 8; ks++) qk_step(SaA, stb, ks);

    // ---- mainloop: ntk is even; unroll x2 to ping-pong S buffers ----
    {
        int sC = 0, sN = 1, sL = 2;
        for (int t = 0; t < ntk; t += 2) {
            body(t,     SaA, SaB, stb + sC*STAGE_B, stb + sN*STAGE_B, stb + sL*STAGE_B);
            body(t + 1, SaB, SaA, stb + sN*STAGE_B, stb + sL*STAGE_B, stb + sC*STAGE_B);
            int tmp = sC; sC = sL; sL = sN; sN = tmp;    // two rotations of (C,N,L)<-(N,L,C)
        }
    }

    // ---- epilogue ----
    lsum0 += __shfl_xor_sync(0xffffffffu, lsum0, 1);
    lsum0 += __shfl_xor_sync(0xffffffffu, lsum0, 2);
    lsum1 += __shfl_xor_sync(0xffffffffu, lsum1, 1);
    lsum1 += __shfl_xor_sync(0xffffffffu, lsum1, 2);
    const float inv0 = 1.0f / lsum0, inv1 = 1.0f / lsum1;

    float* O0 = Og + ((size_t)bh * S_LEN + grow0) * DH;
    float* O1 = O0 + 8 * DH;
    #pragma unroll
    for (int nn2 = 0; nn2 < 16; nn2++) {
        int col = 8 * nn2 + 2 * (l & 3);
        *(float2*)(O0 + col) = make_float2(Oa[nn2][0] * inv0, Oa[nn2][1] * inv0);
        *(float2*)(O1 + col) = make_float2(Oa[nn2][2] * inv1, Oa[nn2][3] * inv1);
    }
}

extern "C" void kernel_launch(void* const* d_in, const int* in_sizes, int n_in,
                              void* d_out, int out_size)
{
    const float* K = (const float*)d_in[0];
    const float* V = (const float*)d_in[1];
    const float* Q = (const float*)d_in[2];
    float* O = (float*)d_out;

    split_prep<<<4096, 256>>>(K, V);

    cudaFuncSetAttribute(fa_mma_kernel,
                         cudaFuncAttributeMaxDynamicSharedMemorySize, SM_TOTAL);
    dim3 grid(S_LEN / QT_ROWS, BH);
    fa_mma_kernel<<<grid, NT, SM_TOTAL>>>(Q, O);
}

// round 7
// speedup vs baseline: 1.5804x; 1.5804x over previous
#include <cuda_runtime.h>
#include <cuda_fp16.h>
#include <stdint.h>

#define S_LEN 2048
#define DH    128
#define BH    64
#define NT    256
#define QT_ROWS 128
#define KT_ROWS 64

#define ELEMS ((size_t)BH * S_LEN * DH)
#define PAIRS (ELEMS / 2)

// fp16 scratch: K hi, V hi (1-term QK, 2-term PV)
__device__ __align__(16) __half g_kh[ELEMS];
__device__ __align__(16) __half g_vh[ELEMS];

// SMEM: Q hi 32KB + two 32KB stages {Kh,Vh} = 96KB
#define SM_QH   0u
#define SM_ST0  32768u
#define STAGE_B 32768u
#define OFF_VH  16384u
#define SM_TOTAL 98304

__device__ __forceinline__ uint32_t pack2h(float x, float y) {
    __half2 h = __floats2half2_rn(x, y);
    return *(uint32_t*)&h;
}
__device__ __forceinline__ void split2h(float x, float y, uint32_t& h, uint32_t& l) {
    __half hx = __float2half_rn(x);
    __half hy = __float2half_rn(y);
    __half lx = __float2half_rn(x - __half2float(hx));
    __half ly = __float2half_rn(y - __half2float(hy));
    h = (uint32_t)__half_as_ushort(hx) | ((uint32_t)__half_as_ushort(hy) << 16);
    l = (uint32_t)__half_as_ushort(lx) | ((uint32_t)__half_as_ushort(ly) << 16);
}

__global__ void split_prep(const float* __restrict__ K, const float* __restrict__ V)
{
    const float2* k2 = (const float2*)K;
    const float2* v2 = (const float2*)V;
    uint32_t* kh = (uint32_t*)g_kh;
    uint32_t* vh = (uint32_t*)g_vh;
    size_t stride = (size_t)gridDim.x * blockDim.x;
    for (size_t i = (size_t)blockIdx.x * blockDim.x + threadIdx.x; i < PAIRS; i += stride) {
        float2 v;
        v = k2[i]; kh[i] = pack2h(v.x, v.y);
        v = v2[i]; vh[i] = pack2h(v.x, v.y);
    }
}

__device__ __forceinline__ uint32_t smem_u32(const void* p) {
    uint32_t a;
    asm("{ .reg .u64 t; cvta.to.shared.u64 t, %1; cvt.u32.u64 %0, t; }" : "=r"(a) : "l"(p));
    return a;
}
__device__ __forceinline__ void cpa16(uint32_t dst, const void* src) {
    asm volatile("cp.async.cg.shared.global [%0], [%1], 16;" :: "r"(dst), "l"(src));
}
#define CP_COMMIT() asm volatile("cp.async.commit_group;" ::: "memory")
#define CP_WAIT1()  asm volatile("cp.async.wait_group 1;" ::: "memory")

#define LDSM_X4(r0,r1,r2,r3,a) \
    asm volatile("ldmatrix.sync.aligned.m8n8.x4.shared.b16 {%0,%1,%2,%3},[%4];" \
                 : "=r"(r0),"=r"(r1),"=r"(r2),"=r"(r3) : "r"(a))
#define LDSM_X4T(r0,r1,r2,r3,a) \
    asm volatile("ldmatrix.sync.aligned.m8n8.x4.trans.shared.b16 {%0,%1,%2,%3},[%4];" \
                 : "=r"(r0),"=r"(r1),"=r"(r2),"=r"(r3) : "r"(a))
#define MMA(c,a0,a1,a2,a3,b0,b1) \
    asm volatile("mma.sync.aligned.m16n8k16.row.col.f32.f16.f16.f32 " \
                 "{%0,%1,%2,%3},{%4,%5,%6,%7},{%8,%9},{%0,%1,%2,%3};" \
                 : "+f"((c)[0]),"+f"((c)[1]),"+f"((c)[2]),"+f"((c)[3]) \
                 : "r"(a0),"r"(a1),"r"(a2),"r"(a3),"r"(b0),"r"(b1))

__global__ __launch_bounds__(NT, 1)
void fa_mma_kernel(const float* __restrict__ Qg_all, float* __restrict__ Og)
{
    extern __shared__ __align__(16) char sm8[];
    const uint32_t smb = smem_u32(sm8);
    const int tid = threadIdx.x;
    const int w = tid >> 5, l = tid & 31;

    const int qt = (int)gridDim.x - 1 - (int)blockIdx.x;   // heaviest first
    const int bh = blockIdx.y;
    const size_t gbase = (size_t)bh * S_LEN * DH;
    const int ntk = 2 * qt + 2;
    const float scale = 0.08838834764831845f;   // 1/sqrt(128)

    // ---- Q prologue: load f32, pre-scale, round to fp16 ----
    {
        const float4* q4 = (const float4*)(Qg_all + gbase + (size_t)qt * QT_ROWS * DH);
        #pragma unroll
        for (int i = 0; i < 8; i++) {
            int it  = tid + i * NT;          // 128 rows x 16 chunks
            int row = it >> 4, ch = it & 15;
            float4 f0 = q4[row * 32 + ch * 2];
            float4 f1 = q4[row * 32 + ch * 2 + 1];
            uint4 hq = make_uint4(pack2h(f0.x*scale, f0.y*scale),
                                  pack2h(f0.z*scale, f0.w*scale),
                                  pack2h(f1.x*scale, f1.y*scale),
                                  pack2h(f1.z*scale, f1.w*scale));
            *(uint4*)(sm8 + SM_QH + (row << 8) + ((ch ^ (row & 7)) << 4)) = hq;
        }
    }

    auto load_kv = [&](int buf, int kti) {
        const uint32_t st = smb + SM_ST0 + (uint32_t)buf * STAGE_B;
        const size_t gb = gbase + (size_t)kti * KT_ROWS * DH;
        #pragma unroll
        for (int i = 0; i < 8; i++) {
            int it  = tid + i * NT;          // 2 arrays x 64 rows x 16 chunks
            int arr = it >> 10;
            int row = (it >> 4) & 63;
            int ch  = it & 15;
            uint32_t dst = st + (uint32_t)arr * 16384u + (row << 8) + ((ch ^ (row & 7)) << 4);
            const __half* sp = (arr == 0) ? g_kh : g_vh;
            cpa16(dst, sp + gb + (size_t)row * DH + ch * 8);
        }
    };
    load_kv(0, 0);
    CP_COMMIT();
    load_kv(1, 1);
    CP_COMMIT();

    float Oa[16][4];
    #pragma unroll
    for (int i = 0; i < 16; i++) { Oa[i][0]=Oa[i][1]=Oa[i][2]=Oa[i][3]=0.f; }
    float lsum0 = 0.f, lsum1 = 0.f;

    const int grow0  = qt * QT_ROWS + 16 * w + (l >> 2);
    const int rowmax = qt * QT_ROWS + 16 * w + 15;
    const uint32_t qrowaddr = smb + SM_QH + (uint32_t)((16 * w + (l & 15)) << 8);
    const int aswz = l & 7;
    const int ainc = l >> 4;

    for (int kt = 0; kt < ntk; kt++) {
        CP_WAIT1();
        __syncthreads();
        const int kbase = kt * KT_ROWS;

        if (kbase <= rowmax) {   // skip fully-masked warps on diagonal tiles
            const uint32_t st  = smb + SM_ST0 + (uint32_t)(kt & 1) * STAGE_B;
            const uint32_t sKH = st, sVH = st + OFF_VH;

            // ---- S = Q @ K^T: 1-term fp16 (qh * kh) ----
            float Sa[8][4];
            #pragma unroll
            for (int i = 0; i < 8; i++) { Sa[i][0]=Sa[i][1]=Sa[i][2]=Sa[i][3]=0.f; }

            #pragma unroll
            for (int ks = 0; ks < 8; ks++) {
                uint32_t qh0,qh1,qh2,qh3;
                uint32_t qa = qrowaddr + (uint32_t)(((2*ks + ainc) ^ aswz) << 4);
                LDSM_X4(qh0,qh1,qh2,qh3, qa);
                uint32_t kh[16];
                #pragma unroll
                for (int p = 0; p < 4; p++) {
                    uint32_t ka = sKH + (uint32_t)((8*(2*p + (l>>4)) + (l & 7)) << 8)
                                      + (uint32_t)(((2*ks + ((l>>3)&1)) ^ aswz) << 4);
                    LDSM_X4(kh[4*p],kh[4*p+1],kh[4*p+2],kh[4*p+3], ka);
                }
                #pragma unroll
                for (int p = 0; p < 4; p++) {
                    MMA(Sa[2*p],   qh0,qh1,qh2,qh3, kh[4*p],  kh[4*p+1]);
                    MMA(Sa[2*p+1], qh0,qh1,qh2,qh3, kh[4*p+2],kh[4*p+3]);
                }
            }

            // ---- fused softmax + PV (2-term fp16), per 16-wide k-group ----
            const bool wfull = (kbase + KT_ROWS - 1) <= (qt * QT_ROWS + 16 * w);
            #pragma unroll
            for (int kv = 0; kv < 4; kv++) {
                uint32_t ph[4], pl[4];
                #pragma unroll
                for (int q = 0; q < 2; q++) {
                    int nn = 2*kv + q;
                    float p00, p01, p10, p11;
                    if (wfull) {
                        p00 = __expf(Sa[nn][0]); p01 = __expf(Sa[nn][1]);
                        p10 = __expf(Sa[nn][2]); p11 = __expf(Sa[nn][3]);
                    } else {
                        int kc = kbase + 8 * nn + 2 * (l & 3);
                        p00 = (kc     <= grow0    ) ? __expf(Sa[nn][0]) : 0.f;
                        p01 = (kc + 1 <= grow0    ) ? __expf(Sa[nn][1]) : 0.f;
                        p10 = (kc     <= grow0 + 8) ? __expf(Sa[nn][2]) : 0.f;
                        p11 = (kc + 1 <= grow0 + 8) ? __expf(Sa[nn][3]) : 0.f;
                    }
                    lsum0 += p00 + p01;
                    lsum1 += p10 + p11;
                    split2h(p00, p01, ph[2*q],   pl[2*q]);
                    split2h(p10, p11, ph[2*q+1], pl[2*q+1]);
                }
                uint32_t vh[32];
                #pragma unroll
                for (int p2 = 0; p2 < 8; p2++) {
                    uint32_t va = sVH + (uint32_t)((16*kv + (l & 15)) << 8)
                                      + (uint32_t)(((2*p2 + (l>>4)) ^ aswz) << 4);
                    LDSM_X4T(vh[4*p2],vh[4*p2+1],vh[4*p2+2],vh[4*p2+3], va);
                }
                #pragma unroll
                for (int p2 = 0; p2 < 8; p2++) {   // sweep 1: Ph * Vh
                    MMA(Oa[2*p2],   ph[0],ph[1],ph[2],ph[3], vh[4*p2],  vh[4*p2+1]);
                    MMA(Oa[2*p2+1], ph[0],ph[1],ph[2],ph[3], vh[4*p2+2],vh[4*p2+3]);
                }
                #pragma unroll
                for (int p2 = 0; p2 < 8; p2++) {   // sweep 2: Pl * Vh
                    MMA(Oa[2*p2],   pl[0],pl[1],pl[2],pl[3], vh[4*p2],  vh[4*p2+1]);
                    MMA(Oa[2*p2+1], pl[0],pl[1],pl[2],pl[3], vh[4*p2+2],vh[4*p2+3]);
                }
            }
        }

        __syncthreads();
        if (kt + 2 < ntk) load_kv(kt & 1, kt + 2);
        CP_COMMIT();
    }

    // ---- epilogue ----
    lsum0 += __shfl_xor_sync(0xffffffffu, lsum0, 1);
    lsum0 += __shfl_xor_sync(0xffffffffu, lsum0, 2);
    lsum1 += __shfl_xor_sync(0xffffffffu, lsum1, 1);
    lsum1 += __shfl_xor_sync(0xffffffffu, lsum1, 2);
    const float inv0 = 1.0f / lsum0, inv1 = 1.0f / lsum1;

    float* O0 = Og + ((size_t)bh * S_LEN + grow0) * DH;
    float* O1 = O0 + 8 * DH;
    #pragma unroll
    for (int nn2 = 0; nn2 < 16; nn2++) {
        int col = 8 * nn2 + 2 * (l & 3);
        *(float2*)(O0 + col) = make_float2(Oa[nn2][0] * inv0, Oa[nn2][1] * inv0);
        *(float2*)(O1 + col) = make_float2(Oa[nn2][2] * inv1, Oa[nn2][3] * inv1);
    }
}

extern "C" void kernel_launch(void* const* d_in, const int* in_sizes, int n_in,
                              void* d_out, int out_size)
{
    const float* K = (const float*)d_in[0];
    const float* V = (const float*)d_in[1];
    const float* Q = (const float*)d_in[2];
    float* O = (float*)d_out;

    split_prep<<<4096, 256>>>(K, V);

    cudaFuncSetAttribute(fa_mma_kernel,
                         cudaFuncAttributeMaxDynamicSharedMemorySize, SM_TOTAL);
    dim3 grid(S_LEN / QT_ROWS, BH);
    fa_mma_kernel<<<grid, NT, SM_TOTAL>>>(Q, O);
}

// round 8
// speedup vs baseline: 2.0736x; 1.3121x over previous
#include <cuda_runtime.h>
#include <cuda_fp16.h>
#include <stdint.h>

#define S_LEN 2048
#define DH    128
#define BH    64
#define NT    256
#define QT_ROWS 128
#define KT_ROWS 64

#define ELEMS ((size_t)BH * S_LEN * DH)
#define PAIRS (ELEMS / 2)

// fp16 scratch: K hi, V hi (1-term QK, 1-term PV)
__device__ __align__(16) __half g_kh[ELEMS];
__device__ __align__(16) __half g_vh[ELEMS];

// SMEM: Q hi 32KB + two 32KB stages {Kh,Vh} = 96KB
#define SM_QH   0u
#define SM_ST0  32768u
#define STAGE_B 32768u
#define OFF_VH  16384u
#define SM_TOTAL 98304

__device__ __forceinline__ uint32_t pack2h(float x, float y) {
    __half2 h = __floats2half2_rn(x, y);
    return *(uint32_t*)&h;
}

__global__ void split_prep(const float* __restrict__ K, const float* __restrict__ V)
{
    const float2* k2 = (const float2*)K;
    const float2* v2 = (const float2*)V;
    uint32_t* kh = (uint32_t*)g_kh;
    uint32_t* vh = (uint32_t*)g_vh;
    size_t stride = (size_t)gridDim.x * blockDim.x;
    for (size_t i = (size_t)blockIdx.x * blockDim.x + threadIdx.x; i < PAIRS; i += stride) {
        float2 v;
        v = k2[i]; kh[i] = pack2h(v.x, v.y);
        v = v2[i]; vh[i] = pack2h(v.x, v.y);
    }
}

__device__ __forceinline__ uint32_t smem_u32(const void* p) {
    uint32_t a;
    asm("{ .reg .u64 t; cvta.to.shared.u64 t, %1; cvt.u32.u64 %0, t; }" : "=r"(a) : "l"(p));
    return a;
}
__device__ __forceinline__ void cpa16(uint32_t dst, const void* src) {
    asm volatile("cp.async.cg.shared.global [%0], [%1], 16;" :: "r"(dst), "l"(src));
}
#define CP_COMMIT() asm volatile("cp.async.commit_group;" ::: "memory")
#define CP_WAIT1()  asm volatile("cp.async.wait_group 1;" ::: "memory")

#define LDSM_X4(r0,r1,r2,r3,a) \
    asm volatile("ldmatrix.sync.aligned.m8n8.x4.shared.b16 {%0,%1,%2,%3},[%4];" \
                 : "=r"(r0),"=r"(r1),"=r"(r2),"=r"(r3) : "r"(a))
#define LDSM_X4T(r0,r1,r2,r3,a) \
    asm volatile("ldmatrix.sync.aligned.m8n8.x4.trans.shared.b16 {%0,%1,%2,%3},[%4];" \
                 : "=r"(r0),"=r"(r1),"=r"(r2),"=r"(r3) : "r"(a))
#define MMA(c,a0,a1,a2,a3,b0,b1) \
    asm volatile("mma.sync.aligned.m16n8k16.row.col.f32.f16.f16.f32 " \
                 "{%0,%1,%2,%3},{%4,%5,%6,%7},{%8,%9},{%0,%1,%2,%3};" \
                 : "+f"((c)[0]),"+f"((c)[1]),"+f"((c)[2]),"+f"((c)[3]) \
                 : "r"(a0),"r"(a1),"r"(a2),"r"(a3),"r"(b0),"r"(b1))

__global__ __launch_bounds__(NT, 1)
void fa_mma_kernel(const float* __restrict__ Qg_all, float* __restrict__ Og)
{
    extern __shared__ __align__(16) char sm8[];
    const uint32_t smb = smem_u32(sm8);
    const int tid = threadIdx.x;
    const int w = tid >> 5, l = tid & 31;

    const int qt = (int)gridDim.x - 1 - (int)blockIdx.x;   // heaviest first
    const int bh = blockIdx.y;
    const size_t gbase = (size_t)bh * S_LEN * DH;
    const int ntk = 2 * qt + 2;
    const float scale = 0.08838834764831845f;   // 1/sqrt(128)

    // ---- Q prologue: load f32, pre-scale, round to fp16 ----
    {
        const float4* q4 = (const float4*)(Qg_all + gbase + (size_t)qt * QT_ROWS * DH);
        #pragma unroll
        for (int i = 0; i < 8; i++) {
            int it  = tid + i * NT;          // 128 rows x 16 chunks
            int row = it >> 4, ch = it & 15;
            float4 f0 = q4[row * 32 + ch * 2];
            float4 f1 = q4[row * 32 + ch * 2 + 1];
            uint4 hq = make_uint4(pack2h(f0.x*scale, f0.y*scale),
                                  pack2h(f0.z*scale, f0.w*scale),
                                  pack2h(f1.x*scale, f1.y*scale),
                                  pack2h(f1.z*scale, f1.w*scale));
            *(uint4*)(sm8 + SM_QH + (row << 8) + ((ch ^ (row & 7)) << 4)) = hq;
        }
    }

    auto load_kv = [&](int buf, int kti) {
        const uint32_t st = smb + SM_ST0 + (uint32_t)buf * STAGE_B;
        const size_t gb = gbase + (size_t)kti * KT_ROWS * DH;
        #pragma unroll
        for (int i = 0; i < 8; i++) {
            int it  = tid + i * NT;          // 2 arrays x 64 rows x 16 chunks
            int arr = it >> 10;
            int row = (it >> 4) & 63;
            int ch  = it & 15;
            uint32_t dst = st + (uint32_t)arr * 16384u + (row << 8) + ((ch ^ (row & 7)) << 4);
            const __half* sp = (arr == 0) ? g_kh : g_vh;
            cpa16(dst, sp + gb + (size_t)row * DH + ch * 8);
        }
    };
    load_kv(0, 0);
    CP_COMMIT();
    load_kv(1, 1);
    CP_COMMIT();

    float Oa[16][4];
    #pragma unroll
    for (int i = 0; i < 16; i++) { Oa[i][0]=Oa[i][1]=Oa[i][2]=Oa[i][3]=0.f; }
    float lsum0 = 0.f, lsum1 = 0.f;

    const int grow0  = qt * QT_ROWS + 16 * w + (l >> 2);
    const int rowmax = qt * QT_ROWS + 16 * w + 15;
    const uint32_t qrowaddr = smb + SM_QH + (uint32_t)((16 * w + (l & 15)) << 8);
    const int aswz = l & 7;
    const int ainc = l >> 4;

    for (int kt = 0; kt < ntk; kt++) {
        CP_WAIT1();
        __syncthreads();
        const int kbase = kt * KT_ROWS;

        if (kbase <= rowmax) {   // skip fully-masked warps on diagonal tiles
            const uint32_t st  = smb + SM_ST0 + (uint32_t)(kt & 1) * STAGE_B;
            const uint32_t sKH = st, sVH = st + OFF_VH;

            // ---- S = Q @ K^T: 1-term fp16 (qh * kh) ----
            float Sa[8][4];
            #pragma unroll
            for (int i = 0; i < 8; i++) { Sa[i][0]=Sa[i][1]=Sa[i][2]=Sa[i][3]=0.f; }

            #pragma unroll
            for (int ks = 0; ks < 8; ks++) {
                uint32_t qh0,qh1,qh2,qh3;
                uint32_t qa = qrowaddr + (uint32_t)(((2*ks + ainc) ^ aswz) << 4);
                LDSM_X4(qh0,qh1,qh2,qh3, qa);
                uint32_t kh[16];
                #pragma unroll
                for (int p = 0; p < 4; p++) {
                    uint32_t ka = sKH + (uint32_t)((8*(2*p + (l>>4)) + (l & 7)) << 8)
                                      + (uint32_t)(((2*ks + ((l>>3)&1)) ^ aswz) << 4);
                    LDSM_X4(kh[4*p],kh[4*p+1],kh[4*p+2],kh[4*p+3], ka);
                }
                #pragma unroll
                for (int p = 0; p < 4; p++) {
                    MMA(Sa[2*p],   qh0,qh1,qh2,qh3, kh[4*p],  kh[4*p+1]);
                    MMA(Sa[2*p+1], qh0,qh1,qh2,qh3, kh[4*p+2],kh[4*p+3]);
                }
            }

            // ---- fused softmax + PV (1-term fp16), per 16-wide k-group ----
            const bool wfull = (kbase + KT_ROWS - 1) <= (qt * QT_ROWS + 16 * w);
            #pragma unroll
            for (int kv = 0; kv < 4; kv++) {
                uint32_t ph[4];
                #pragma unroll
                for (int q = 0; q < 2; q++) {
                    int nn = 2*kv + q;
                    float p00, p01, p10, p11;
                    if (wfull) {
                        p00 = __expf(Sa[nn][0]); p01 = __expf(Sa[nn][1]);
                        p10 = __expf(Sa[nn][2]); p11 = __expf(Sa[nn][3]);
                    } else {
                        int kc = kbase + 8 * nn + 2 * (l & 3);
                        p00 = (kc     <= grow0    ) ? __expf(Sa[nn][0]) : 0.f;
                        p01 = (kc + 1 <= grow0    ) ? __expf(Sa[nn][1]) : 0.f;
                        p10 = (kc     <= grow0 + 8) ? __expf(Sa[nn][2]) : 0.f;
                        p11 = (kc + 1 <= grow0 + 8) ? __expf(Sa[nn][3]) : 0.f;
                    }
                    lsum0 += p00 + p01;
                    lsum1 += p10 + p11;
                    ph[2*q]   = pack2h(p00, p01);
                    ph[2*q+1] = pack2h(p10, p11);
                }
                uint32_t vh[32];
                #pragma unroll
                for (int p2 = 0; p2 < 8; p2++) {
                    uint32_t va = sVH + (uint32_t)((16*kv + (l & 15)) << 8)
                                      + (uint32_t)(((2*p2 + (l>>4)) ^ aswz) << 4);
                    LDSM_X4T(vh[4*p2],vh[4*p2+1],vh[4*p2+2],vh[4*p2+3], va);
                }
                #pragma unroll
                for (int p2 = 0; p2 < 8; p2++) {   // single sweep: Ph * Vh
                    MMA(Oa[2*p2],   ph[0],ph[1],ph[2],ph[3], vh[4*p2],  vh[4*p2+1]);
                    MMA(Oa[2*p2+1], ph[0],ph[1],ph[2],ph[3], vh[4*p2+2],vh[4*p2+3]);
                }
            }
        }

        __syncthreads();
        if (kt + 2 < ntk) load_kv(kt & 1, kt + 2);
        CP_COMMIT();
    }

    // ---- epilogue ----
    lsum0 += __shfl_xor_sync(0xffffffffu, lsum0, 1);
    lsum0 += __shfl_xor_sync(0xffffffffu, lsum0, 2);
    lsum1 += __shfl_xor_sync(0xffffffffu, lsum1, 1);
    lsum1 += __shfl_xor_sync(0xffffffffu, lsum1, 2);
    const float inv0 = 1.0f / lsum0, inv1 = 1.0f / lsum1;

    float* O0 = Og + ((size_t)bh * S_LEN + grow0) * DH;
    float* O1 = O0 + 8 * DH;
    #pragma unroll
    for (int nn2 = 0; nn2 < 16; nn2++) {
        int col = 8 * nn2 + 2 * (l & 3);
        *(float2*)(O0 + col) = make_float2(Oa[nn2][0] * inv0, Oa[nn2][1] * inv0);
        *(float2*)(O1 + col) = make_float2(Oa[nn2][2] * inv1, Oa[nn2][3] * inv1);
    }
}

extern "C" void kernel_launch(void* const* d_in, const int* in_sizes, int n_in,
                              void* d_out, int out_size)
{
    const float* K = (const float*)d_in[0];
    const float* V = (const float*)d_in[1];
    const float* Q = (const float*)d_in[2];
    float* O = (float*)d_out;

    split_prep<<<4096, 256>>>(K, V);

    cudaFuncSetAttribute(fa_mma_kernel,
                         cudaFuncAttributeMaxDynamicSharedMemorySize, SM_TOTAL);
    dim3 grid(S_LEN / QT_ROWS, BH);
    fa_mma_kernel<<<grid, NT, SM_TOTAL>>>(Q, O);
}